// round 16
// baseline (speedup 1.0000x reference)
#include <cuda_runtime.h>
#include <cuda.h>
#include <cuda_bf16.h>
#include <math.h>
#include <stdint.h>

#define BB 16
#define SS 2048
#define DD 256
#define LDQKV 768
#define NROWS ((size_t)BB * SS)

// split-bf16 planes
__device__ __nv_bfloat16 g_xh[(size_t)BB * SS * DD];
__device__ __nv_bfloat16 g_xl[(size_t)BB * SS * DD];
__device__ __nv_bfloat16 g_wqh[(size_t)LDQKV * DD];
__device__ __nv_bfloat16 g_wql[(size_t)LDQKV * DD];
__device__ __nv_bfloat16 g_woh[(size_t)DD * DD];
__device__ __nv_bfloat16 g_wol[(size_t)DD * DD];
__device__ __nv_bfloat16 g_qkv_h[(size_t)BB * SS * LDQKV];
__device__ __nv_bfloat16 g_qkv_l[(size_t)BB * SS * LDQKV];
__device__ __nv_bfloat16 g_ctx_h[(size_t)BB * SS * DD];
__device__ __nv_bfloat16 g_ctx_l[(size_t)BB * SS * DD];
// split-K attention partials (un-normalized, fp32) + tickets
__device__ float g_part[2 * NROWS * DD];
__device__ float g_lsum[2 * NROWS];
__device__ int   g_tick[BB * 32];   // zero-init; reset by last block each run

// ===========================================================================
// primitives
// ===========================================================================
__device__ __forceinline__ void mma16816(float& c0, float& c1, float& c2, float& c3,
    uint32_t a0, uint32_t a1, uint32_t a2, uint32_t a3, uint32_t b0, uint32_t b1)
{
    asm volatile(
        "mma.sync.aligned.m16n8k16.row.col.f32.bf16.bf16.f32 "
        "{%0,%1,%2,%3},{%4,%5,%6,%7},{%8,%9},{%0,%1,%2,%3};\n"
        : "+f"(c0), "+f"(c1), "+f"(c2), "+f"(c3)
        : "r"(a0), "r"(a1), "r"(a2), "r"(a3), "r"(b0), "r"(b1));
}
__device__ __forceinline__ void ldsm4(uint32_t addr, uint32_t& r0, uint32_t& r1, uint32_t& r2, uint32_t& r3)
{
    asm volatile("ldmatrix.sync.aligned.m8n8.x4.shared.b16 {%0,%1,%2,%3},[%4];\n"
        : "=r"(r0), "=r"(r1), "=r"(r2), "=r"(r3) : "r"(addr));
}
__device__ __forceinline__ void ldsm4t(uint32_t addr, uint32_t& r0, uint32_t& r1, uint32_t& r2, uint32_t& r3)
{
    asm volatile("ldmatrix.sync.aligned.m8n8.x4.trans.shared.b16 {%0,%1,%2,%3},[%4];\n"
        : "=r"(r0), "=r"(r1), "=r"(r2), "=r"(r3) : "r"(addr));
}
__device__ __forceinline__ void tma2d(uint32_t dst, const CUtensorMap* tm,
                                      int x, int y, uint32_t mbar)
{
    asm volatile(
        "cp.async.bulk.tensor.2d.shared::cta.global.tile.mbarrier::complete_tx::bytes "
        "[%0], [%1, {%2, %3}], [%4];\n"
        :: "r"(dst), "l"(tm), "r"(x), "r"(y), "r"(mbar) : "memory");
}
#define MB_INIT(mb, c) \
    asm volatile("mbarrier.init.shared.b64 [%0], %1;" :: "r"(mb), "r"(c) : "memory")
#define MB_EXPECT(mb, b) \
    asm volatile("mbarrier.arrive.expect_tx.shared.b64 _, [%0], %1;" :: "r"(mb), "r"(b) : "memory")
__device__ __forceinline__ void mbar_wait(uint32_t mbar, uint32_t parity)
{
    asm volatile(
        "{\n\t.reg .pred P;\n\t"
        "W_%=:\n\t"
        "mbarrier.try_wait.parity.acquire.cta.shared::cta.b64 P, [%0], %1, 0x989680;\n\t"
        "@!P bra.uni W_%=;\n\t}"
        :: "r"(mbar), "r"(parity) : "memory");
}
__device__ __forceinline__ float ex2(float x)
{
    float y;
    asm("ex2.approx.ftz.f32 %0, %1;" : "=f"(y) : "f"(x));
    return y;
}

// ===========================================================================
// merged fp32 -> bf16 hi/lo splitter (x | w_qkv | w_out in one launch)
// ===========================================================================
#define NX4  (BB * SS * DD / 4)
#define NWQ4 (LDQKV * DD / 4)
#define NWO4 (DD * DD / 4)
// Q pre-scale = (1/16) * log2(e): softmax uses ex2 directly
#define QSCL 0.0901684165f

__global__ void __launch_bounds__(256) split_all(
    const float* __restrict__ x, const float* __restrict__ wq,
    const float* __restrict__ wo)
{
    int i = blockIdx.x * 256 + threadIdx.x;
    const float* src;
    __nv_bfloat16 *h, *l;
    float s = 1.0f;
    int j = i;
    if (i < NX4) {
        src = x; h = g_xh; l = g_xl;
    } else if (i < NX4 + NWQ4) {
        j = i - NX4;
        src = wq; h = g_wqh; l = g_wql;
        if (j < DD * DD / 4) s = QSCL;
    } else if (i < NX4 + NWQ4 + NWO4) {
        j = i - NX4 - NWQ4;
        src = wo; h = g_woh; l = g_wol;
    } else return;

    float4 v = ((const float4*)src)[j];
    v.x *= s; v.y *= s; v.z *= s; v.w *= s;
    __nv_bfloat162 h01 = __floats2bfloat162_rn(v.x, v.y);
    __nv_bfloat162 h23 = __floats2bfloat162_rn(v.z, v.w);
    __nv_bfloat162 l01 = __floats2bfloat162_rn(v.x - __bfloat162float(h01.x),
                                               v.y - __bfloat162float(h01.y));
    __nv_bfloat162 l23 = __floats2bfloat162_rn(v.z - __bfloat162float(h23.x),
                                               v.w - __bfloat162float(h23.y));
    ((uint2*)h)[j] = make_uint2(*(uint32_t*)&h01, *(uint32_t*)&h23);
    ((uint2*)l)[j] = make_uint2(*(uint32_t*)&l01, *(uint32_t*)&l23);
}

// ===========================================================================
// Split-bf16 tensor-core GEMM (round-12, unchanged): 128x64 tile, 8 warps,
// BK=64, 2-stage TMA pipeline, 2 CTAs/SM.
// ===========================================================================
#define GST   49152
#define GMB   98304
#define GSMEM 98368

template <int MODE>
__global__ void __launch_bounds__(256, 2) gemm_tma(
    const __grid_constant__ CUtensorMap tAh, const __grid_constant__ CUtensorMap tAl,
    const __grid_constant__ CUtensorMap tBh, const __grid_constant__ CUtensorMap tBl,
    const float* __restrict__ bias,
    __nv_bfloat16* __restrict__ Ch, __nv_bfloat16* __restrict__ Cl,
    float* __restrict__ Cf, int ldc)
{
    extern __shared__ __align__(1024) char sm[];
    const uint32_t su = (uint32_t)__cvta_generic_to_shared(sm);
    const uint32_t mb0 = su + GMB, mb1 = mb0 + 8;

    const int tid  = threadIdx.x;
    const int w    = tid >> 5;
    const int lane = tid & 31;
    const int wm = w & 3;
    const int wn = w >> 2;
    const int l8 = lane & 7;
    const int lb = (lane >> 3) & 1;
    const int lc = lane >> 4;
    const int gid = lane >> 2;
    const int tig = lane & 3;
    const int arow = l8 + (lb << 3);
    const int brow = l8 + (lc << 3);

    const int m0i = blockIdx.y << 7;
    const int n0  = blockIdx.x << 6;
    const size_t m0 = (size_t)m0i;

    float acc[2][4][4];
#pragma unroll
    for (int mt = 0; mt < 2; ++mt)
#pragma unroll
        for (int nc = 0; nc < 4; ++nc)
#pragma unroll
            for (int c = 0; c < 4; ++c) acc[mt][nc][c] = 0.f;

    if (tid == 0) { MB_INIT(mb0, 1); MB_INIT(mb1, 1); }
    __syncthreads();
    if (tid == 0) {
        MB_EXPECT(mb0, (uint32_t)GST);
        tma2d(su,         &tAh, 0, m0i, mb0);
        tma2d(su + 16384, &tAl, 0, m0i, mb0);
        tma2d(su + 32768, &tBh, 0, n0,  mb0);
        tma2d(su + 40960, &tBl, 0, n0,  mb0);
    }

#pragma unroll
    for (int ki = 0; ki < 4; ++ki) {
        mbar_wait((ki & 1) ? mb1 : mb0, (uint32_t)((ki >> 1) & 1));
        __syncthreads();

        if (ki < 3 && tid == 0) {
            const uint32_t st = su + (((ki + 1) & 1) ? GST : 0u);
            const uint32_t mbx = ((ki + 1) & 1) ? mb1 : mb0;
            const int k0 = (ki + 1) << 6;
            MB_EXPECT(mbx, (uint32_t)GST);
            tma2d(st,         &tAh, k0, m0i, mbx);
            tma2d(st + 16384, &tAl, k0, m0i, mbx);
            tma2d(st + 32768, &tBh, k0, n0,  mbx);
            tma2d(st + 40960, &tBl, k0, n0,  mbx);
        }

        const uint32_t sb  = su + ((ki & 1) ? GST : 0u);
        const uint32_t uAh = sb, uAl = sb + 16384, uBh = sb + 32768, uBl = sb + 40960;

#pragma unroll
        for (int kc = 0; kc < 4; ++kc) {
            const uint32_t ca = (uint32_t)((((kc << 1) + lc) ^ l8) << 4);
            const uint32_t cb = (uint32_t)((((kc << 1) + lb) ^ l8) << 4);
            uint32_t ah[2][4], al[2][4];
#pragma unroll
            for (int mt = 0; mt < 2; ++mt) {
                const uint32_t ra = (uint32_t)(((wm << 5) + (mt << 4) + arow) << 7);
                ldsm4(uAh + ra + ca, ah[mt][0], ah[mt][1], ah[mt][2], ah[mt][3]);
                ldsm4(uAl + ra + ca, al[mt][0], al[mt][1], al[mt][2], al[mt][3]);
            }
#pragma unroll
            for (int nt = 0; nt < 2; ++nt) {
                const uint32_t rb = (uint32_t)(((wn << 5) + (nt << 4) + brow) << 7);
                uint32_t bh0, bh1, bh2, bh3, bl0, bl1, bl2, bl3;
                ldsm4(uBh + rb + cb, bh0, bh1, bh2, bh3);
                ldsm4(uBl + rb + cb, bl0, bl1, bl2, bl3);
#pragma unroll
                for (int mt = 0; mt < 2; ++mt) {
                    float* o0 = acc[mt][nt << 1];
                    float* o1 = acc[mt][(nt << 1) + 1];
                    mma16816(o0[0], o0[1], o0[2], o0[3],
                             ah[mt][0], ah[mt][1], ah[mt][2], ah[mt][3], bh0, bh1);
                    mma16816(o0[0], o0[1], o0[2], o0[3],
                             ah[mt][0], ah[mt][1], ah[mt][2], ah[mt][3], bl0, bl1);
                    mma16816(o0[0], o0[1], o0[2], o0[3],
                             al[mt][0], al[mt][1], al[mt][2], al[mt][3], bh0, bh1);
                    mma16816(o1[0], o1[1], o1[2], o1[3],
                             ah[mt][0], ah[mt][1], ah[mt][2], ah[mt][3], bh2, bh3);
                    mma16816(o1[0], o1[1], o1[2], o1[3],
                             ah[mt][0], ah[mt][1], ah[mt][2], ah[mt][3], bl2, bl3);
                    mma16816(o1[0], o1[1], o1[2], o1[3],
                             al[mt][0], al[mt][1], al[mt][2], al[mt][3], bh2, bh3);
                }
            }
        }
    }

#pragma unroll
    for (int mt = 0; mt < 2; ++mt) {
        const size_t r0 = m0 + (wm << 5) + (mt << 4) + gid;
#pragma unroll
        for (int nc = 0; nc < 4; ++nc) {
            const int col = n0 + (wn << 5) + (nc << 3) + (tig << 1);
            float v0 = acc[mt][nc][0], v1 = acc[mt][nc][1];
            float v2 = acc[mt][nc][2], v3 = acc[mt][nc][3];
            if (MODE == 0) {
                __nv_bfloat162 h01 = __floats2bfloat162_rn(v0, v1);
                __nv_bfloat162 h23 = __floats2bfloat162_rn(v2, v3);
                __nv_bfloat162 l01 = __floats2bfloat162_rn(v0 - __bfloat162float(h01.x),
                                                           v1 - __bfloat162float(h01.y));
                __nv_bfloat162 l23 = __floats2bfloat162_rn(v2 - __bfloat162float(h23.x),
                                                           v3 - __bfloat162float(h23.y));
                *(uint32_t*)(Ch + r0 * ldc + col)       = *(uint32_t*)&h01;
                *(uint32_t*)(Ch + (r0 + 8) * ldc + col) = *(uint32_t*)&h23;
                *(uint32_t*)(Cl + r0 * ldc + col)       = *(uint32_t*)&l01;
                *(uint32_t*)(Cl + (r0 + 8) * ldc + col) = *(uint32_t*)&l23;
            } else {
                float bx = bias[col], by = bias[col + 1];
                *(float2*)&Cf[r0 * ldc + col]       = make_float2(v0 + bx, v1 + by);
                *(float2*)&Cf[(r0 + 8) * ldc + col] = make_float2(v2 + bx, v3 + by);
            }
        }
    }
}

// ===========================================================================
// Flash attention, static softmax (ex2), split-K=2, 256 threads, TMA Q/K/V.
// Round-16: combine folded in via ticket — last block per (b,qt) merges its
// register partials with the partner's gmem partials and writes ctx planes.
// ===========================================================================
#define SM_QH   0
#define SM_QL   32768
#define SM_KH   65536
#define SM_KL   98304
#define SM_VH   131072
#define SM_VL   163840
#define SM_PH   196608
#define SM_PL   204800
#define SM_STAT 212992
#define SM_MBQ  214016
#define SM_MBK  214024
#define SM_MBV  214032
#define SM_TOTAL 214080

__global__ void __launch_bounds__(256, 1) attn_kernel(
    const __grid_constant__ CUtensorMap tqh, const __grid_constant__ CUtensorMap tql)
{
    extern __shared__ __align__(1024) char smx[];
    float* psum = (float*)(smx + SM_STAT);        // [2][64]
    float* lrow = psum + 128;                     // [64]
    int*   sold = (int*)(psum + 192);

    const int tid  = threadIdx.x;
    const int w    = tid >> 5;
    const int lane = tid & 31;
    const int gid  = lane >> 2;
    const int tig  = lane & 3;
    const int half = w >> 2;
    const int sr0  = (w & 3) << 4;
    const int sn0  = half << 5;
    const int wr  = w & 1;
    const int wd2 = w >> 1;

    const int b  = blockIdx.y;
    const int qt = blockIdx.x;
    const int kz = blockIdx.z;
    const int yq = b * SS + qt * 64;
    const int h0 = kz << 4;

    const int l8 = lane & 7;
    const int lb = (lane >> 3) & 1;
    const int lc = lane >> 4;
    const int ksw  = l8;
    const int arow = l8 + (lb << 3);
    const int brow = l8 + (lc << 3);

    const uint32_t su   = (uint32_t)__cvta_generic_to_shared(smx);
    const uint32_t s_qh = su + SM_QH, s_ql = su + SM_QL;
    const uint32_t s_kh = su + SM_KH, s_kl = su + SM_KL;
    const uint32_t s_vh = su + SM_VH, s_vl = su + SM_VL;
    const uint32_t s_ph = su + SM_PH, s_pl = su + SM_PL;
    const uint32_t mbQ = su + SM_MBQ, mbK = su + SM_MBK, mbV = su + SM_MBV;

    const uint32_t qa_row = s_qh + ((sr0 + arow) << 7);
    const uint32_t qa_rwl = s_ql + ((sr0 + arow) << 7);

    if (tid == 0) { MB_INIT(mbQ, 1); MB_INIT(mbK, 1); MB_INIT(mbV, 1); }
    __syncthreads();
    if (tid == 0) {
        MB_EXPECT(mbQ, 65536u);
#pragma unroll
        for (int g = 0; g < 4; ++g) {
            tma2d(s_qh + (g << 13), &tqh, g << 6, yq, mbQ);
            tma2d(s_ql + (g << 13), &tql, g << 6, yq, mbQ);
        }
        MB_EXPECT(mbK, 65536u);
#pragma unroll
        for (int g = 0; g < 4; ++g) {
            tma2d(s_kh + (g << 13), &tqh, 256 + (g << 6), b * SS + h0 * 64, mbK);
            tma2d(s_kl + (g << 13), &tql, 256 + (g << 6), b * SS + h0 * 64, mbK);
        }
    }

    float oacc[2][8][4];
#pragma unroll
    for (int mt = 0; mt < 2; ++mt)
#pragma unroll
        for (int ng = 0; ng < 8; ++ng)
#pragma unroll
            for (int c = 0; c < 4; ++c) oacc[mt][ng][c] = 0.f;

    float lsum0 = 0.f, lsum1 = 0.f;

    const int NTL = 16;
    for (int ktl = 0; ktl < NTL; ++ktl) {
        const int yk = b * SS + (h0 + ktl) * 64;

        mbar_wait(mbK, (uint32_t)(ktl & 1));
        if (ktl == 0) mbar_wait(mbQ, 0u);
        __syncthreads();

        if (tid == 0) {
            MB_EXPECT(mbV, 65536u);
#pragma unroll
            for (int g = 0; g < 4; ++g) {
                tma2d(s_vh + (g << 13), &tqh, 512 + (g << 6), yk, mbV);
                tma2d(s_vl + (g << 13), &tql, 512 + (g << 6), yk, mbV);
            }
        }

        // ---------------- scores ----------------
        float sfr[4][4];
#pragma unroll
        for (int nc = 0; nc < 4; ++nc)
#pragma unroll
            for (int c = 0; c < 4; ++c) sfr[nc][c] = 0.f;

#pragma unroll 4
        for (int k0 = 0; k0 < DD; k0 += 16) {
            const int c0 = k0 >> 3;
            const uint32_t goff = (uint32_t)((c0 >> 3) << 13);
            const uint32_t ja = (uint32_t)(((((c0 & 7) + lc)) ^ ksw) << 4);
            const uint32_t jb = (uint32_t)(((((c0 & 7) + lb)) ^ ksw) << 4);
            uint32_t ah0, ah1, ah2, ah3, al0, al1, al2, al3;
            ldsm4(qa_row + goff + ja, ah0, ah1, ah2, ah3);
            ldsm4(qa_rwl + goff + ja, al0, al1, al2, al3);
#pragma unroll
            for (int pr = 0; pr < 2; ++pr) {
                const int key = sn0 + (pr << 4) + brow;
                const uint32_t koff = goff + (key << 7) + jb;
                uint32_t bh0, bh1, bh2, bh3, bl0, bl1, bl2, bl3;
                ldsm4(s_kh + koff, bh0, bh1, bh2, bh3);
                ldsm4(s_kl + koff, bl0, bl1, bl2, bl3);
                float* s0 = sfr[pr << 1];
                float* s1 = sfr[(pr << 1) + 1];
                mma16816(s0[0], s0[1], s0[2], s0[3], ah0, ah1, ah2, ah3, bh0, bh1);
                mma16816(s0[0], s0[1], s0[2], s0[3], ah0, ah1, ah2, ah3, bl0, bl1);
                mma16816(s0[0], s0[1], s0[2], s0[3], al0, al1, al2, al3, bh0, bh1);
                mma16816(s1[0], s1[1], s1[2], s1[3], ah0, ah1, ah2, ah3, bh2, bh3);
                mma16816(s1[0], s1[1], s1[2], s1[3], ah0, ah1, ah2, ah3, bl2, bl3);
                mma16816(s1[0], s1[1], s1[2], s1[3], al0, al1, al2, al3, bh2, bh3);
            }
        }

        // ---------------- static softmax: p = 2^(s') (log2e folded into Q) --
        const int poff0 = ((sr0 + gid) << 7) + (tig << 2);
        const int poff1 = ((sr0 + gid + 8) << 7) + (tig << 2);
#pragma unroll
        for (int nc = 0; nc < 4; ++nc) {
            float p0 = ex2(sfr[nc][0]);
            float p1 = ex2(sfr[nc][1]);
            float p2 = ex2(sfr[nc][2]);
            float p3 = ex2(sfr[nc][3]);
            lsum0 += p0 + p1;
            lsum1 += p2 + p3;
            __nv_bfloat162 h01 = __floats2bfloat162_rn(p0, p1);
            __nv_bfloat162 h23 = __floats2bfloat162_rn(p2, p3);
            __nv_bfloat162 l01 = __floats2bfloat162_rn(p0 - __bfloat162float(h01.x),
                                                       p1 - __bfloat162float(h01.y));
            __nv_bfloat162 l23 = __floats2bfloat162_rn(p2 - __bfloat162float(h23.x),
                                                       p3 - __bfloat162float(h23.y));
            const int ch = (half << 2) + nc;
            const int sw0 = ((ch ^ gid) << 4);
            *(uint32_t*)(smx + SM_PH + poff0 + sw0) = *(uint32_t*)&h01;
            *(uint32_t*)(smx + SM_PH + poff1 + sw0) = *(uint32_t*)&h23;
            *(uint32_t*)(smx + SM_PL + poff0 + sw0) = *(uint32_t*)&l01;
            *(uint32_t*)(smx + SM_PL + poff1 + sw0) = *(uint32_t*)&l23;
        }

        __syncthreads();

        if (ktl + 1 < NTL && tid == 0) {
            MB_EXPECT(mbK, 65536u);
#pragma unroll
            for (int g = 0; g < 4; ++g) {
                tma2d(s_kh + (g << 13), &tqh, 256 + (g << 6), yk + 64, mbK);
                tma2d(s_kl + (g << 13), &tql, 256 + (g << 6), yk + 64, mbK);
            }
        }

        mbar_wait(mbV, (uint32_t)(ktl & 1));

        // ---------------- PV: warp = 32 rows x 64 dims ----------------
#pragma unroll
        for (int kk0 = 0; kk0 < 64; kk0 += 16) {
            uint32_t ph[2][4], pl[2][4];
            const uint32_t kc = ((((kk0 >> 3) + lc) ^ ksw) << 4);
#pragma unroll
            for (int mt = 0; mt < 2; ++mt) {
                const uint32_t pao = (uint32_t)((((wr << 5) + (mt << 4) + arow) << 7)) + kc;
                ldsm4(s_ph + pao, ph[mt][0], ph[mt][1], ph[mt][2], ph[mt][3]);
                ldsm4(s_pl + pao, pl[mt][0], pl[mt][1], pl[mt][2], pl[mt][3]);
            }
            const int vkey = kk0 + arow;
#pragma unroll
            for (int j = 0; j < 4; ++j) {
                const int cn = (wd2 << 3) + (j << 1);
                const uint32_t voff = (uint32_t)((cn >> 3) << 13) + (vkey << 7)
                                    + (uint32_t)(((((cn & 7) + lc)) ^ ksw) << 4);
                uint32_t vh0, vh1, vh2, vh3, vl0, vl1, vl2, vl3;
                ldsm4t(s_vh + voff, vh0, vh1, vh2, vh3);
                ldsm4t(s_vl + voff, vl0, vl1, vl2, vl3);
#pragma unroll
                for (int mt = 0; mt < 2; ++mt) {
                    float* o0 = oacc[mt][j << 1];
                    float* o1 = oacc[mt][(j << 1) + 1];
                    mma16816(o0[0], o0[1], o0[2], o0[3],
                             ph[mt][0], ph[mt][1], ph[mt][2], ph[mt][3], vh0, vh1);
                    mma16816(o0[0], o0[1], o0[2], o0[3],
                             ph[mt][0], ph[mt][1], ph[mt][2], ph[mt][3], vl0, vl1);
                    mma16816(o0[0], o0[1], o0[2], o0[3],
                             pl[mt][0], pl[mt][1], pl[mt][2], pl[mt][3], vh0, vh1);
                    mma16816(o1[0], o1[1], o1[2], o1[3],
                             ph[mt][0], ph[mt][1], ph[mt][2], ph[mt][3], vh2, vh3);
                    mma16816(o1[0], o1[1], o1[2], o1[3],
                             ph[mt][0], ph[mt][1], ph[mt][2], ph[mt][3], vl2, vl3);
                    mma16816(o1[0], o1[1], o1[2], o1[3],
                             pl[mt][0], pl[mt][1], pl[mt][2], pl[mt][3], vh2, vh3);
                }
            }
        }
    }

    // ---------------- epilogue: partial store + ticket combine ----------------
    lsum0 += __shfl_xor_sync(0xffffffffu, lsum0, 1);
    lsum0 += __shfl_xor_sync(0xffffffffu, lsum0, 2);
    lsum1 += __shfl_xor_sync(0xffffffffu, lsum1, 1);
    lsum1 += __shfl_xor_sync(0xffffffffu, lsum1, 2);
    if (tig == 0) {
        psum[(half << 6) + sr0 + gid]     = lsum0;
        psum[(half << 6) + sr0 + gid + 8] = lsum1;
    }
    __syncthreads();
    if (tid < 64) {
        float lv = psum[tid] + psum[64 + tid];
        lrow[tid] = lv;
        g_lsum[(size_t)kz * NROWS + yq + tid] = lv;
    }

    float* gp = g_part + (size_t)kz * NROWS * DD;
#pragma unroll
    for (int mt = 0; mt < 2; ++mt) {
        const int r0i = (wr << 5) + (mt << 4) + gid;
        const size_t row0 = (size_t)yq + r0i;
#pragma unroll
        for (int ng = 0; ng < 8; ++ng) {
            const int col = (wd2 << 6) + (ng << 3) + (tig << 1);
            *(float2*)(gp + row0 * DD + col)       = make_float2(oacc[mt][ng][0], oacc[mt][ng][1]);
            *(float2*)(gp + (row0 + 8) * DD + col) = make_float2(oacc[mt][ng][2], oacc[mt][ng][3]);
        }
    }

    __threadfence();           // release own partial + lsum
    __syncthreads();           // all threads' stores fenced before the ticket
    if (tid == 0) *sold = atomicAdd(&g_tick[b * 32 + qt], 1);
    __syncthreads();

    if (*sold == 1) {
        __threadfence();       // acquire partner's stores
        const int pz = 1 - kz;
        const float* pp  = g_part + (size_t)pz * NROWS * DD;
        const float* plm = g_lsum + (size_t)pz * NROWS + yq;
#pragma unroll
        for (int mt = 0; mt < 2; ++mt) {
            const int r0i = (wr << 5) + (mt << 4) + gid;
            const size_t row0 = (size_t)yq + r0i;
            const float il0 = 1.f / (lrow[r0i]     + plm[r0i]);
            const float il1 = 1.f / (lrow[r0i + 8] + plm[r0i + 8]);
#pragma unroll
            for (int ng = 0; ng < 8; ++ng) {
                const int col = (wd2 << 6) + (ng << 3) + (tig << 1);
                float2 q0 = *(const float2*)(pp + row0 * DD + col);
                float2 q1 = *(const float2*)(pp + (row0 + 8) * DD + col);
                float o00 = (oacc[mt][ng][0] + q0.x) * il0;
                float o01 = (oacc[mt][ng][1] + q0.y) * il0;
                float o10 = (oacc[mt][ng][2] + q1.x) * il1;
                float o11 = (oacc[mt][ng][3] + q1.y) * il1;
                __nv_bfloat162 h0 = __floats2bfloat162_rn(o00, o01);
                __nv_bfloat162 h1 = __floats2bfloat162_rn(o10, o11);
                __nv_bfloat162 l0 = __floats2bfloat162_rn(o00 - __bfloat162float(h0.x),
                                                          o01 - __bfloat162float(h0.y));
                __nv_bfloat162 l1 = __floats2bfloat162_rn(o10 - __bfloat162float(h1.x),
                                                          o11 - __bfloat162float(h1.y));
                *(uint32_t*)(g_ctx_h + row0 * DD + col)       = *(uint32_t*)&h0;
                *(uint32_t*)(g_ctx_h + (row0 + 8) * DD + col) = *(uint32_t*)&h1;
                *(uint32_t*)(g_ctx_l + row0 * DD + col)       = *(uint32_t*)&l0;
                *(uint32_t*)(g_ctx_l + (row0 + 8) * DD + col) = *(uint32_t*)&l1;
            }
        }
        if (tid == 0) g_tick[b * 32 + qt] = 0;   // deterministic across replays
    }
}

// ===========================================================================
// host side
// ===========================================================================
typedef CUresult (*PFN_tmEncode)(
    CUtensorMap*, CUtensorMapDataType, cuuint32_t, void*,
    const cuuint64_t*, const cuuint64_t*, const cuuint32_t*, const cuuint32_t*,
    CUtensorMapInterleave, CUtensorMapSwizzle, CUtensorMapL2promotion,
    CUtensorMapFloatOOBfill);

static void make_tm(PFN_tmEncode enc, CUtensorMap* tm, void* base,
                    uint64_t d0, uint64_t d1, uint32_t b0, uint32_t b1)
{
    cuuint64_t dims[2] = {d0, d1};
    cuuint64_t strides[1] = {d0 * 2};
    cuuint32_t box[2] = {b0, b1};
    cuuint32_t es[2] = {1, 1};
    enc(tm, CU_TENSOR_MAP_DATA_TYPE_BFLOAT16, 2, base, dims, strides, box, es,
        CU_TENSOR_MAP_INTERLEAVE_NONE, CU_TENSOR_MAP_SWIZZLE_128B,
        CU_TENSOR_MAP_L2_PROMOTION_L2_128B, CU_TENSOR_MAP_FLOAT_OOB_FILL_NONE);
}

extern "C" void kernel_launch(void* const* d_in, const int* in_sizes, int n_in,
                              void* d_out, int out_size)
{
    const float* x     = (const float*)d_in[0];
    const float* w_qkv = (const float*)d_in[1];
    const float* w_out = (const float*)d_in[2];
    const float* b_out = (const float*)d_in[3];
    float* out = (float*)d_out;

    __nv_bfloat16 *xh, *xl, *wqh, *wql, *woh, *wol, *qh, *ql, *ch, *cl;
    cudaGetSymbolAddress((void**)&xh,  g_xh);
    cudaGetSymbolAddress((void**)&xl,  g_xl);
    cudaGetSymbolAddress((void**)&wqh, g_wqh);
    cudaGetSymbolAddress((void**)&wql, g_wql);
    cudaGetSymbolAddress((void**)&woh, g_woh);
    cudaGetSymbolAddress((void**)&wol, g_wol);
    cudaGetSymbolAddress((void**)&qh,  g_qkv_h);
    cudaGetSymbolAddress((void**)&ql,  g_qkv_l);
    cudaGetSymbolAddress((void**)&ch,  g_ctx_h);
    cudaGetSymbolAddress((void**)&cl,  g_ctx_l);

    PFN_tmEncode enc = nullptr;
    cudaDriverEntryPointQueryResult qres;
    cudaGetDriverEntryPoint("cuTensorMapEncodeTiled", (void**)&enc,
                            cudaEnableDefault, &qres);

    CUtensorMap tqh, tql, txh, txl, twqh, twql, tch, tcl, twoh, twol;
    make_tm(enc, &tqh,  qh,  LDQKV, (uint64_t)BB * SS, 64, 64);
    make_tm(enc, &tql,  ql,  LDQKV, (uint64_t)BB * SS, 64, 64);
    make_tm(enc, &txh,  xh,  DD, (uint64_t)BB * SS, 64, 128);
    make_tm(enc, &txl,  xl,  DD, (uint64_t)BB * SS, 64, 128);
    make_tm(enc, &tch,  ch,  DD, (uint64_t)BB * SS, 64, 128);
    make_tm(enc, &tcl,  cl,  DD, (uint64_t)BB * SS, 64, 128);
    make_tm(enc, &twqh, wqh, DD, LDQKV, 64, 64);
    make_tm(enc, &twql, wql, DD, LDQKV, 64, 64);
    make_tm(enc, &twoh, woh, DD, DD, 64, 64);
    make_tm(enc, &twol, wol, DD, DD, 64, 64);

    cudaFuncSetAttribute(attn_kernel, cudaFuncAttributeMaxDynamicSharedMemorySize, SM_TOTAL);
    cudaFuncSetAttribute(gemm_tma<0>, cudaFuncAttributeMaxDynamicSharedMemorySize, GSMEM);
    cudaFuncSetAttribute(gemm_tma<1>, cudaFuncAttributeMaxDynamicSharedMemorySize, GSMEM);

    const int ntot = NX4 + NWQ4 + NWO4;
    split_all<<<(ntot + 255) / 256, 256>>>(x, w_qkv, w_out);

    gemm_tma<0><<<dim3(LDQKV / 64, (BB * SS) / 128), 256, GSMEM>>>(
        txh, txl, twqh, twql, nullptr, qh, ql, nullptr, LDQKV);

    attn_kernel<<<dim3(SS / 64, BB, 2), 256, SM_TOTAL>>>(tqh, tql);

    gemm_tma<1><<<dim3(DD / 64, (BB * SS) / 128), 256, GSMEM>>>(
        tch, tcl, twoh, twol, b_out, nullptr, nullptr, out, DD);
}

// round 17
// speedup vs baseline: 1.0391x; 1.0391x over previous
#include <cuda_runtime.h>
#include <cuda.h>
#include <cuda_bf16.h>
#include <math.h>
#include <stdint.h>

#define BB 16
#define SS 2048
#define DD 256
#define LDQKV 768
#define NROWS ((size_t)BB * SS)

// split-bf16 planes
__device__ __nv_bfloat16 g_xh[(size_t)BB * SS * DD];
__device__ __nv_bfloat16 g_xl[(size_t)BB * SS * DD];
__device__ __nv_bfloat16 g_wqh[(size_t)LDQKV * DD];
__device__ __nv_bfloat16 g_wql[(size_t)LDQKV * DD];
__device__ __nv_bfloat16 g_woh[(size_t)DD * DD];
__device__ __nv_bfloat16 g_wol[(size_t)DD * DD];
__device__ __nv_bfloat16 g_qkv_h[(size_t)BB * SS * LDQKV];
__device__ __nv_bfloat16 g_qkv_l[(size_t)BB * SS * LDQKV];
__device__ __nv_bfloat16 g_ctx_h[(size_t)BB * SS * DD];
__device__ __nv_bfloat16 g_ctx_l[(size_t)BB * SS * DD];
// split-K attention partials (un-normalized, fp32)
__device__ float g_part[2 * NROWS * DD];
__device__ float g_lsum[2 * NROWS];

// ===========================================================================
// primitives
// ===========================================================================
__device__ __forceinline__ void mma16816(float& c0, float& c1, float& c2, float& c3,
    uint32_t a0, uint32_t a1, uint32_t a2, uint32_t a3, uint32_t b0, uint32_t b1)
{
    asm volatile(
        "mma.sync.aligned.m16n8k16.row.col.f32.bf16.bf16.f32 "
        "{%0,%1,%2,%3},{%4,%5,%6,%7},{%8,%9},{%0,%1,%2,%3};\n"
        : "+f"(c0), "+f"(c1), "+f"(c2), "+f"(c3)
        : "r"(a0), "r"(a1), "r"(a2), "r"(a3), "r"(b0), "r"(b1));
}
__device__ __forceinline__ void ldsm4(uint32_t addr, uint32_t& r0, uint32_t& r1, uint32_t& r2, uint32_t& r3)
{
    asm volatile("ldmatrix.sync.aligned.m8n8.x4.shared.b16 {%0,%1,%2,%3},[%4];\n"
        : "=r"(r0), "=r"(r1), "=r"(r2), "=r"(r3) : "r"(addr));
}
__device__ __forceinline__ void ldsm4t(uint32_t addr, uint32_t& r0, uint32_t& r1, uint32_t& r2, uint32_t& r3)
{
    asm volatile("ldmatrix.sync.aligned.m8n8.x4.trans.shared.b16 {%0,%1,%2,%3},[%4];\n"
        : "=r"(r0), "=r"(r1), "=r"(r2), "=r"(r3) : "r"(addr));
}
__device__ __forceinline__ void tma2d(uint32_t dst, const CUtensorMap* tm,
                                      int x, int y, uint32_t mbar)
{
    asm volatile(
        "cp.async.bulk.tensor.2d.shared::cta.global.tile.mbarrier::complete_tx::bytes "
        "[%0], [%1, {%2, %3}], [%4];\n"
        :: "r"(dst), "l"(tm), "r"(x), "r"(y), "r"(mbar) : "memory");
}
#define MB_INIT(mb, c) \
    asm volatile("mbarrier.init.shared.b64 [%0], %1;" :: "r"(mb), "r"(c) : "memory")
#define MB_EXPECT(mb, b) \
    asm volatile("mbarrier.arrive.expect_tx.shared.b64 _, [%0], %1;" :: "r"(mb), "r"(b) : "memory")
__device__ __forceinline__ void mbar_wait(uint32_t mbar, uint32_t parity)
{
    asm volatile(
        "{\n\t.reg .pred P;\n\t"
        "W_%=:\n\t"
        "mbarrier.try_wait.parity.acquire.cta.shared::cta.b64 P, [%0], %1, 0x989680;\n\t"
        "@!P bra.uni W_%=;\n\t}"
        :: "r"(mbar), "r"(parity) : "memory");
}
__device__ __forceinline__ float ex2(float x)
{
    float y;
    asm("ex2.approx.ftz.f32 %0, %1;" : "=f"(y) : "f"(x));
    return y;
}

// ===========================================================================
// merged fp32 -> bf16 hi/lo splitter (x | w_qkv | w_out in one launch)
// ===========================================================================
#define NX4  (BB * SS * DD / 4)
#define NWQ4 (LDQKV * DD / 4)
#define NWO4 (DD * DD / 4)
// Q pre-scale = (1/16) * log2(e): softmax uses ex2 directly
#define QSCL 0.0901684165f

__global__ void __launch_bounds__(256) split_all(
    const float* __restrict__ x, const float* __restrict__ wq,
    const float* __restrict__ wo)
{
    int i = blockIdx.x * 256 + threadIdx.x;
    const float* src;
    __nv_bfloat16 *h, *l;
    float s = 1.0f;
    int j = i;
    if (i < NX4) {
        src = x; h = g_xh; l = g_xl;
    } else if (i < NX4 + NWQ4) {
        j = i - NX4;
        src = wq; h = g_wqh; l = g_wql;
        if (j < DD * DD / 4) s = QSCL;
    } else if (i < NX4 + NWQ4 + NWO4) {
        j = i - NX4 - NWQ4;
        src = wo; h = g_woh; l = g_wol;
    } else return;

    float4 v = ((const float4*)src)[j];
    v.x *= s; v.y *= s; v.z *= s; v.w *= s;
    __nv_bfloat162 h01 = __floats2bfloat162_rn(v.x, v.y);
    __nv_bfloat162 h23 = __floats2bfloat162_rn(v.z, v.w);
    __nv_bfloat162 l01 = __floats2bfloat162_rn(v.x - __bfloat162float(h01.x),
                                               v.y - __bfloat162float(h01.y));
    __nv_bfloat162 l23 = __floats2bfloat162_rn(v.z - __bfloat162float(h23.x),
                                               v.w - __bfloat162float(h23.y));
    ((uint2*)h)[j] = make_uint2(*(uint32_t*)&h01, *(uint32_t*)&h23);
    ((uint2*)l)[j] = make_uint2(*(uint32_t*)&l01, *(uint32_t*)&l23);
}

// ===========================================================================
// combine kernel: ctx = (part0 + part1) / (l0 + l1), emit bf16 hi/lo planes
// ===========================================================================
__global__ void __launch_bounds__(256) combine_k()
{
    int i = blockIdx.x * 256 + threadIdx.x;
    if (i >= (int)(NROWS * (DD / 4))) return;
    int row = i >> 6;
    int c4 = (i & 63) << 2;
    float il = 1.f / (g_lsum[row] + g_lsum[NROWS + row]);
    float4 a = *(const float4*)(g_part + (size_t)row * DD + c4);
    float4 b = *(const float4*)(g_part + NROWS * DD + (size_t)row * DD + c4);
    float o0 = (a.x + b.x) * il, o1 = (a.y + b.y) * il;
    float o2 = (a.z + b.z) * il, o3 = (a.w + b.w) * il;
    __nv_bfloat162 h01 = __floats2bfloat162_rn(o0, o1);
    __nv_bfloat162 h23 = __floats2bfloat162_rn(o2, o3);
    __nv_bfloat162 l01 = __floats2bfloat162_rn(o0 - __bfloat162float(h01.x),
                                               o1 - __bfloat162float(h01.y));
    __nv_bfloat162 l23 = __floats2bfloat162_rn(o2 - __bfloat162float(h23.x),
                                               o3 - __bfloat162float(h23.y));
    *(uint2*)(g_ctx_h + (size_t)row * DD + c4) = make_uint2(*(uint32_t*)&h01, *(uint32_t*)&h23);
    *(uint2*)(g_ctx_l + (size_t)row * DD + c4) = make_uint2(*(uint32_t*)&l01, *(uint32_t*)&l23);
}

// ===========================================================================
// Split-bf16 tensor-core GEMM (round-12, unchanged): 128x64 tile, 8 warps,
// BK=64, 2-stage TMA pipeline, 2 CTAs/SM.
// ===========================================================================
#define GST   49152
#define GMB   98304
#define GSMEM 98368

template <int MODE>
__global__ void __launch_bounds__(256, 2) gemm_tma(
    const __grid_constant__ CUtensorMap tAh, const __grid_constant__ CUtensorMap tAl,
    const __grid_constant__ CUtensorMap tBh, const __grid_constant__ CUtensorMap tBl,
    const float* __restrict__ bias,
    __nv_bfloat16* __restrict__ Ch, __nv_bfloat16* __restrict__ Cl,
    float* __restrict__ Cf, int ldc)
{
    extern __shared__ __align__(1024) char sm[];
    const uint32_t su = (uint32_t)__cvta_generic_to_shared(sm);
    const uint32_t mb0 = su + GMB, mb1 = mb0 + 8;

    const int tid  = threadIdx.x;
    const int w    = tid >> 5;
    const int lane = tid & 31;
    const int wm = w & 3;
    const int wn = w >> 2;
    const int l8 = lane & 7;
    const int lb = (lane >> 3) & 1;
    const int lc = lane >> 4;
    const int gid = lane >> 2;
    const int tig = lane & 3;
    const int arow = l8 + (lb << 3);
    const int brow = l8 + (lc << 3);

    const int m0i = blockIdx.y << 7;
    const int n0  = blockIdx.x << 6;
    const size_t m0 = (size_t)m0i;

    float acc[2][4][4];
#pragma unroll
    for (int mt = 0; mt < 2; ++mt)
#pragma unroll
        for (int nc = 0; nc < 4; ++nc)
#pragma unroll
            for (int c = 0; c < 4; ++c) acc[mt][nc][c] = 0.f;

    if (tid == 0) { MB_INIT(mb0, 1); MB_INIT(mb1, 1); }
    __syncthreads();
    if (tid == 0) {
        MB_EXPECT(mb0, (uint32_t)GST);
        tma2d(su,         &tAh, 0, m0i, mb0);
        tma2d(su + 16384, &tAl, 0, m0i, mb0);
        tma2d(su + 32768, &tBh, 0, n0,  mb0);
        tma2d(su + 40960, &tBl, 0, n0,  mb0);
    }

#pragma unroll
    for (int ki = 0; ki < 4; ++ki) {
        mbar_wait((ki & 1) ? mb1 : mb0, (uint32_t)((ki >> 1) & 1));
        __syncthreads();

        if (ki < 3 && tid == 0) {
            const uint32_t st = su + (((ki + 1) & 1) ? GST : 0u);
            const uint32_t mbx = ((ki + 1) & 1) ? mb1 : mb0;
            const int k0 = (ki + 1) << 6;
            MB_EXPECT(mbx, (uint32_t)GST);
            tma2d(st,         &tAh, k0, m0i, mbx);
            tma2d(st + 16384, &tAl, k0, m0i, mbx);
            tma2d(st + 32768, &tBh, k0, n0,  mbx);
            tma2d(st + 40960, &tBl, k0, n0,  mbx);
        }

        const uint32_t sb  = su + ((ki & 1) ? GST : 0u);
        const uint32_t uAh = sb, uAl = sb + 16384, uBh = sb + 32768, uBl = sb + 40960;

#pragma unroll
        for (int kc = 0; kc < 4; ++kc) {
            const uint32_t ca = (uint32_t)((((kc << 1) + lc) ^ l8) << 4);
            const uint32_t cb = (uint32_t)((((kc << 1) + lb) ^ l8) << 4);
            uint32_t ah[2][4], al[2][4];
#pragma unroll
            for (int mt = 0; mt < 2; ++mt) {
                const uint32_t ra = (uint32_t)(((wm << 5) + (mt << 4) + arow) << 7);
                ldsm4(uAh + ra + ca, ah[mt][0], ah[mt][1], ah[mt][2], ah[mt][3]);
                ldsm4(uAl + ra + ca, al[mt][0], al[mt][1], al[mt][2], al[mt][3]);
            }
#pragma unroll
            for (int nt = 0; nt < 2; ++nt) {
                const uint32_t rb = (uint32_t)(((wn << 5) + (nt << 4) + brow) << 7);
                uint32_t bh0, bh1, bh2, bh3, bl0, bl1, bl2, bl3;
                ldsm4(uBh + rb + cb, bh0, bh1, bh2, bh3);
                ldsm4(uBl + rb + cb, bl0, bl1, bl2, bl3);
#pragma unroll
                for (int mt = 0; mt < 2; ++mt) {
                    float* o0 = acc[mt][nt << 1];
                    float* o1 = acc[mt][(nt << 1) + 1];
                    mma16816(o0[0], o0[1], o0[2], o0[3],
                             ah[mt][0], ah[mt][1], ah[mt][2], ah[mt][3], bh0, bh1);
                    mma16816(o0[0], o0[1], o0[2], o0[3],
                             ah[mt][0], ah[mt][1], ah[mt][2], ah[mt][3], bl0, bl1);
                    mma16816(o0[0], o0[1], o0[2], o0[3],
                             al[mt][0], al[mt][1], al[mt][2], al[mt][3], bh0, bh1);
                    mma16816(o1[0], o1[1], o1[2], o1[3],
                             ah[mt][0], ah[mt][1], ah[mt][2], ah[mt][3], bh2, bh3);
                    mma16816(o1[0], o1[1], o1[2], o1[3],
                             ah[mt][0], ah[mt][1], ah[mt][2], ah[mt][3], bl2, bl3);
                    mma16816(o1[0], o1[1], o1[2], o1[3],
                             al[mt][0], al[mt][1], al[mt][2], al[mt][3], bh2, bh3);
                }
            }
        }
    }

#pragma unroll
    for (int mt = 0; mt < 2; ++mt) {
        const size_t r0 = m0 + (wm << 5) + (mt << 4) + gid;
#pragma unroll
        for (int nc = 0; nc < 4; ++nc) {
            const int col = n0 + (wn << 5) + (nc << 3) + (tig << 1);
            float v0 = acc[mt][nc][0], v1 = acc[mt][nc][1];
            float v2 = acc[mt][nc][2], v3 = acc[mt][nc][3];
            if (MODE == 0) {
                __nv_bfloat162 h01 = __floats2bfloat162_rn(v0, v1);
                __nv_bfloat162 h23 = __floats2bfloat162_rn(v2, v3);
                __nv_bfloat162 l01 = __floats2bfloat162_rn(v0 - __bfloat162float(h01.x),
                                                           v1 - __bfloat162float(h01.y));
                __nv_bfloat162 l23 = __floats2bfloat162_rn(v2 - __bfloat162float(h23.x),
                                                           v3 - __bfloat162float(h23.y));
                *(uint32_t*)(Ch + r0 * ldc + col)       = *(uint32_t*)&h01;
                *(uint32_t*)(Ch + (r0 + 8) * ldc + col) = *(uint32_t*)&h23;
                *(uint32_t*)(Cl + r0 * ldc + col)       = *(uint32_t*)&l01;
                *(uint32_t*)(Cl + (r0 + 8) * ldc + col) = *(uint32_t*)&l23;
            } else {
                float bx = bias[col], by = bias[col + 1];
                *(float2*)&Cf[r0 * ldc + col]       = make_float2(v0 + bx, v1 + by);
                *(float2*)&Cf[(r0 + 8) * ldc + col] = make_float2(v2 + bx, v3 + by);
            }
        }
    }
}

// ===========================================================================
// Flash attention, static softmax (ex2), split-K=2, 256 threads, TMA Q/K/V.
// (R15 structure: partials to gmem, separate combine kernel)
// ===========================================================================
#define SM_QH   0
#define SM_QL   32768
#define SM_KH   65536
#define SM_KL   98304
#define SM_VH   131072
#define SM_VL   163840
#define SM_PH   196608
#define SM_PL   204800
#define SM_STAT 212992
#define SM_MBQ  213504
#define SM_MBK  213512
#define SM_MBV  213520
#define SM_TOTAL 213568

__global__ void __launch_bounds__(256, 1) attn_kernel(
    const __grid_constant__ CUtensorMap tqh, const __grid_constant__ CUtensorMap tql)
{
    extern __shared__ __align__(1024) char smx[];
    float* psum = (float*)(smx + SM_STAT);

    const int tid  = threadIdx.x;
    const int w    = tid >> 5;
    const int lane = tid & 31;
    const int gid  = lane >> 2;
    const int tig  = lane & 3;
    const int half = w >> 2;
    const int sr0  = (w & 3) << 4;
    const int sn0  = half << 5;
    const int wr  = w & 1;
    const int wd2 = w >> 1;

    const int b  = blockIdx.y;
    const int qt = blockIdx.x;
    const int kz = blockIdx.z;
    const int yq = b * SS + qt * 64;
    const int h0 = kz << 4;

    const int l8 = lane & 7;
    const int lb = (lane >> 3) & 1;
    const int lc = lane >> 4;
    const int ksw  = l8;
    const int arow = l8 + (lb << 3);
    const int brow = l8 + (lc << 3);

    const uint32_t su   = (uint32_t)__cvta_generic_to_shared(smx);
    const uint32_t s_qh = su + SM_QH, s_ql = su + SM_QL;
    const uint32_t s_kh = su + SM_KH, s_kl = su + SM_KL;
    const uint32_t s_vh = su + SM_VH, s_vl = su + SM_VL;
    const uint32_t s_ph = su + SM_PH, s_pl = su + SM_PL;
    const uint32_t mbQ = su + SM_MBQ, mbK = su + SM_MBK, mbV = su + SM_MBV;

    const uint32_t qa_row = s_qh + ((sr0 + arow) << 7);
    const uint32_t qa_rwl = s_ql + ((sr0 + arow) << 7);

    if (tid == 0) { MB_INIT(mbQ, 1); MB_INIT(mbK, 1); MB_INIT(mbV, 1); }
    __syncthreads();
    if (tid == 0) {
        MB_EXPECT(mbQ, 65536u);
#pragma unroll
        for (int g = 0; g < 4; ++g) {
            tma2d(s_qh + (g << 13), &tqh, g << 6, yq, mbQ);
            tma2d(s_ql + (g << 13), &tql, g << 6, yq, mbQ);
        }
        MB_EXPECT(mbK, 65536u);
#pragma unroll
        for (int g = 0; g < 4; ++g) {
            tma2d(s_kh + (g << 13), &tqh, 256 + (g << 6), b * SS + h0 * 64, mbK);
            tma2d(s_kl + (g << 13), &tql, 256 + (g << 6), b * SS + h0 * 64, mbK);
        }
    }

    float oacc[2][8][4];
#pragma unroll
    for (int mt = 0; mt < 2; ++mt)
#pragma unroll
        for (int ng = 0; ng < 8; ++ng)
#pragma unroll
            for (int c = 0; c < 4; ++c) oacc[mt][ng][c] = 0.f;

    float lsum0 = 0.f, lsum1 = 0.f;

    const int NTL = 16;
    for (int ktl = 0; ktl < NTL; ++ktl) {
        const int yk = b * SS + (h0 + ktl) * 64;

        mbar_wait(mbK, (uint32_t)(ktl & 1));
        if (ktl == 0) mbar_wait(mbQ, 0u);
        __syncthreads();

        if (tid == 0) {
            MB_EXPECT(mbV, 65536u);
#pragma unroll
            for (int g = 0; g < 4; ++g) {
                tma2d(s_vh + (g << 13), &tqh, 512 + (g << 6), yk, mbV);
                tma2d(s_vl + (g << 13), &tql, 512 + (g << 6), yk, mbV);
            }
        }

        // ---------------- scores ----------------
        float sfr[4][4];
#pragma unroll
        for (int nc = 0; nc < 4; ++nc)
#pragma unroll
            for (int c = 0; c < 4; ++c) sfr[nc][c] = 0.f;

#pragma unroll 4
        for (int k0 = 0; k0 < DD; k0 += 16) {
            const int c0 = k0 >> 3;
            const uint32_t goff = (uint32_t)((c0 >> 3) << 13);
            const uint32_t ja = (uint32_t)(((((c0 & 7) + lc)) ^ ksw) << 4);
            const uint32_t jb = (uint32_t)(((((c0 & 7) + lb)) ^ ksw) << 4);
            uint32_t ah0, ah1, ah2, ah3, al0, al1, al2, al3;
            ldsm4(qa_row + goff + ja, ah0, ah1, ah2, ah3);
            ldsm4(qa_rwl + goff + ja, al0, al1, al2, al3);
#pragma unroll
            for (int pr = 0; pr < 2; ++pr) {
                const int key = sn0 + (pr << 4) + brow;
                const uint32_t koff = goff + (key << 7) + jb;
                uint32_t bh0, bh1, bh2, bh3, bl0, bl1, bl2, bl3;
                ldsm4(s_kh + koff, bh0, bh1, bh2, bh3);
                ldsm4(s_kl + koff, bl0, bl1, bl2, bl3);
                float* s0 = sfr[pr << 1];
                float* s1 = sfr[(pr << 1) + 1];
                mma16816(s0[0], s0[1], s0[2], s0[3], ah0, ah1, ah2, ah3, bh0, bh1);
                mma16816(s0[0], s0[1], s0[2], s0[3], ah0, ah1, ah2, ah3, bl0, bl1);
                mma16816(s0[0], s0[1], s0[2], s0[3], al0, al1, al2, al3, bh0, bh1);
                mma16816(s1[0], s1[1], s1[2], s1[3], ah0, ah1, ah2, ah3, bh2, bh3);
                mma16816(s1[0], s1[1], s1[2], s1[3], ah0, ah1, ah2, ah3, bl2, bl3);
                mma16816(s1[0], s1[1], s1[2], s1[3], al0, al1, al2, al3, bh2, bh3);
            }
        }

        // ---------------- static softmax: p = 2^(s') ----------------
        const int poff0 = ((sr0 + gid) << 7) + (tig << 2);
        const int poff1 = ((sr0 + gid + 8) << 7) + (tig << 2);
#pragma unroll
        for (int nc = 0; nc < 4; ++nc) {
            float p0 = ex2(sfr[nc][0]);
            float p1 = ex2(sfr[nc][1]);
            float p2 = ex2(sfr[nc][2]);
            float p3 = ex2(sfr[nc][3]);
            lsum0 += p0 + p1;
            lsum1 += p2 + p3;
            __nv_bfloat162 h01 = __floats2bfloat162_rn(p0, p1);
            __nv_bfloat162 h23 = __floats2bfloat162_rn(p2, p3);
            __nv_bfloat162 l01 = __floats2bfloat162_rn(p0 - __bfloat162float(h01.x),
                                                       p1 - __bfloat162float(h01.y));
            __nv_bfloat162 l23 = __floats2bfloat162_rn(p2 - __bfloat162float(h23.x),
                                                       p3 - __bfloat162float(h23.y));
            const int ch = (half << 2) + nc;
            const int sw0 = ((ch ^ gid) << 4);
            *(uint32_t*)(smx + SM_PH + poff0 + sw0) = *(uint32_t*)&h01;
            *(uint32_t*)(smx + SM_PH + poff1 + sw0) = *(uint32_t*)&h23;
            *(uint32_t*)(smx + SM_PL + poff0 + sw0) = *(uint32_t*)&l01;
            *(uint32_t*)(smx + SM_PL + poff1 + sw0) = *(uint32_t*)&l23;
        }

        __syncthreads();

        if (ktl + 1 < NTL && tid == 0) {
            MB_EXPECT(mbK, 65536u);
#pragma unroll
            for (int g = 0; g < 4; ++g) {
                tma2d(s_kh + (g << 13), &tqh, 256 + (g << 6), yk + 64, mbK);
                tma2d(s_kl + (g << 13), &tql, 256 + (g << 6), yk + 64, mbK);
            }
        }

        mbar_wait(mbV, (uint32_t)(ktl & 1));

        // ---------------- PV: warp = 32 rows x 64 dims ----------------
#pragma unroll
        for (int kk0 = 0; kk0 < 64; kk0 += 16) {
            uint32_t ph[2][4], pl[2][4];
            const uint32_t kc = ((((kk0 >> 3) + lc) ^ ksw) << 4);
#pragma unroll
            for (int mt = 0; mt < 2; ++mt) {
                const uint32_t pao = (uint32_t)((((wr << 5) + (mt << 4) + arow) << 7)) + kc;
                ldsm4(s_ph + pao, ph[mt][0], ph[mt][1], ph[mt][2], ph[mt][3]);
                ldsm4(s_pl + pao, pl[mt][0], pl[mt][1], pl[mt][2], pl[mt][3]);
            }
            const int vkey = kk0 + arow;
#pragma unroll
            for (int j = 0; j < 4; ++j) {
                const int cn = (wd2 << 3) + (j << 1);
                const uint32_t voff = (uint32_t)((cn >> 3) << 13) + (vkey << 7)
                                    + (uint32_t)(((((cn & 7) + lc)) ^ ksw) << 4);
                uint32_t vh0, vh1, vh2, vh3, vl0, vl1, vl2, vl3;
                ldsm4t(s_vh + voff, vh0, vh1, vh2, vh3);
                ldsm4t(s_vl + voff, vl0, vl1, vl2, vl3);
#pragma unroll
                for (int mt = 0; mt < 2; ++mt) {
                    float* o0 = oacc[mt][j << 1];
                    float* o1 = oacc[mt][(j << 1) + 1];
                    mma16816(o0[0], o0[1], o0[2], o0[3],
                             ph[mt][0], ph[mt][1], ph[mt][2], ph[mt][3], vh0, vh1);
                    mma16816(o0[0], o0[1], o0[2], o0[3],
                             ph[mt][0], ph[mt][1], ph[mt][2], ph[mt][3], vl0, vl1);
                    mma16816(o0[0], o0[1], o0[2], o0[3],
                             pl[mt][0], pl[mt][1], pl[mt][2], pl[mt][3], vh0, vh1);
                    mma16816(o1[0], o1[1], o1[2], o1[3],
                             ph[mt][0], ph[mt][1], ph[mt][2], ph[mt][3], vh2, vh3);
                    mma16816(o1[0], o1[1], o1[2], o1[3],
                             ph[mt][0], ph[mt][1], ph[mt][2], ph[mt][3], vl2, vl3);
                    mma16816(o1[0], o1[1], o1[2], o1[3],
                             pl[mt][0], pl[mt][1], pl[mt][2], pl[mt][3], vh2, vh3);
                }
            }
        }
    }

    // ---------------- emit partials (un-normalized) ----------------
    lsum0 += __shfl_xor_sync(0xffffffffu, lsum0, 1);
    lsum0 += __shfl_xor_sync(0xffffffffu, lsum0, 2);
    lsum1 += __shfl_xor_sync(0xffffffffu, lsum1, 1);
    lsum1 += __shfl_xor_sync(0xffffffffu, lsum1, 2);
    if (tig == 0) {
        psum[(half << 6) + sr0 + gid]     = lsum0;
        psum[(half << 6) + sr0 + gid + 8] = lsum1;
    }
    __syncthreads();

    if (tid < 64)
        g_lsum[(size_t)kz * NROWS + yq + tid] = psum[tid] + psum[64 + tid];

    float* gp = g_part + (size_t)kz * NROWS * DD;
#pragma unroll
    for (int mt = 0; mt < 2; ++mt) {
        const int r0i = (wr << 5) + (mt << 4) + gid;
        const size_t row0 = (size_t)yq + r0i;
#pragma unroll
        for (int ng = 0; ng < 8; ++ng) {
            const int col = (wd2 << 6) + (ng << 3) + (tig << 1);
            *(float2*)(gp + row0 * DD + col)       = make_float2(oacc[mt][ng][0], oacc[mt][ng][1]);
            *(float2*)(gp + (row0 + 8) * DD + col) = make_float2(oacc[mt][ng][2], oacc[mt][ng][3]);
        }
    }
}

// ===========================================================================
// host side
// ===========================================================================
typedef CUresult (*PFN_tmEncode)(
    CUtensorMap*, CUtensorMapDataType, cuuint32_t, void*,
    const cuuint64_t*, const cuuint64_t*, const cuuint32_t*, const cuuint32_t*,
    CUtensorMapInterleave, CUtensorMapSwizzle, CUtensorMapL2promotion,
    CUtensorMapFloatOOBfill);

static void make_tm(PFN_tmEncode enc, CUtensorMap* tm, void* base,
                    uint64_t d0, uint64_t d1, uint32_t b0, uint32_t b1)
{
    cuuint64_t dims[2] = {d0, d1};
    cuuint64_t strides[1] = {d0 * 2};
    cuuint32_t box[2] = {b0, b1};
    cuuint32_t es[2] = {1, 1};
    enc(tm, CU_TENSOR_MAP_DATA_TYPE_BFLOAT16, 2, base, dims, strides, box, es,
        CU_TENSOR_MAP_INTERLEAVE_NONE, CU_TENSOR_MAP_SWIZZLE_128B,
        CU_TENSOR_MAP_L2_PROMOTION_L2_128B, CU_TENSOR_MAP_FLOAT_OOB_FILL_NONE);
}

extern "C" void kernel_launch(void* const* d_in, const int* in_sizes, int n_in,
                              void* d_out, int out_size)
{
    const float* x     = (const float*)d_in[0];
    const float* w_qkv = (const float*)d_in[1];
    const float* w_out = (const float*)d_in[2];
    const float* b_out = (const float*)d_in[3];
    float* out = (float*)d_out;

    __nv_bfloat16 *xh, *xl, *wqh, *wql, *woh, *wol, *qh, *ql, *ch, *cl;
    cudaGetSymbolAddress((void**)&xh,  g_xh);
    cudaGetSymbolAddress((void**)&xl,  g_xl);
    cudaGetSymbolAddress((void**)&wqh, g_wqh);
    cudaGetSymbolAddress((void**)&wql, g_wql);
    cudaGetSymbolAddress((void**)&woh, g_woh);
    cudaGetSymbolAddress((void**)&wol, g_wol);
    cudaGetSymbolAddress((void**)&qh,  g_qkv_h);
    cudaGetSymbolAddress((void**)&ql,  g_qkv_l);
    cudaGetSymbolAddress((void**)&ch,  g_ctx_h);
    cudaGetSymbolAddress((void**)&cl,  g_ctx_l);

    PFN_tmEncode enc = nullptr;
    cudaDriverEntryPointQueryResult qres;
    cudaGetDriverEntryPoint("cuTensorMapEncodeTiled", (void**)&enc,
                            cudaEnableDefault, &qres);

    CUtensorMap tqh, tql, txh, txl, twqh, twql, tch, tcl, twoh, twol;
    make_tm(enc, &tqh,  qh,  LDQKV, (uint64_t)BB * SS, 64, 64);
    make_tm(enc, &tql,  ql,  LDQKV, (uint64_t)BB * SS, 64, 64);
    make_tm(enc, &txh,  xh,  DD, (uint64_t)BB * SS, 64, 128);
    make_tm(enc, &txl,  xl,  DD, (uint64_t)BB * SS, 64, 128);
    make_tm(enc, &tch,  ch,  DD, (uint64_t)BB * SS, 64, 128);
    make_tm(enc, &tcl,  cl,  DD, (uint64_t)BB * SS, 64, 128);
    make_tm(enc, &twqh, wqh, DD, LDQKV, 64, 64);
    make_tm(enc, &twql, wql, DD, LDQKV, 64, 64);
    make_tm(enc, &twoh, woh, DD, DD, 64, 64);
    make_tm(enc, &twol, wol, DD, DD, 64, 64);

    cudaFuncSetAttribute(attn_kernel, cudaFuncAttributeMaxDynamicSharedMemorySize, SM_TOTAL);
    cudaFuncSetAttribute(gemm_tma<0>, cudaFuncAttributeMaxDynamicSharedMemorySize, GSMEM);
    cudaFuncSetAttribute(gemm_tma<1>, cudaFuncAttributeMaxDynamicSharedMemorySize, GSMEM);

    const int ntot = NX4 + NWQ4 + NWO4;
    split_all<<<(ntot + 255) / 256, 256>>>(x, w_qkv, w_out);

    gemm_tma<0><<<dim3(LDQKV / 64, (BB * SS) / 128), 256, GSMEM>>>(
        txh, txl, twqh, twql, nullptr, qh, ql, nullptr, LDQKV);

    attn_kernel<<<dim3(SS / 64, BB, 2), 256, SM_TOTAL>>>(tqh, tql);

    const int ncomb = (int)(NROWS * (DD / 4));
    combine_k<<<(ncomb + 255) / 256, 256>>>();

    gemm_tma<1><<<dim3(DD / 64, (BB * SS) / 128), 256, GSMEM>>>(
        tch, tcl, twoh, twol, b_out, nullptr, nullptr, out, DD);
}